// round 4
// baseline (speedup 1.0000x reference)
#include <cuda_runtime.h>
#include <cstdint>

// Problem constants (shapes fixed by the dataset)
static constexpr int NMAX = 50000;
static constexpr int EMAX = 800000;

// Scratch (static device allocations — no cudaMalloc allowed).
// __align__(16): these are accessed via float4 and red.global.add.v4.f32.
__device__ __align__(16) float g_deg[NMAX];
__device__ __align__(16) float g_dinv[NMAX];
__device__ __align__(16) float g_sn[NMAX];                 // dinv^2 (self-loop norm)
__device__ __align__(16) float g_H1[(size_t)NMAX * 256];   // x @ W1
__device__ __align__(16) float g_AG1[(size_t)NMAX * 256];  // aggregated layer1
__device__ __align__(16) float g_H2[(size_t)NMAX * 128];   // relu(AG1+b1) @ W2
__device__ __align__(16) float g_AG2[(size_t)NMAX * 128];  // aggregated layer2
__device__ __align__(16) int   g_row[EMAX];
__device__ __align__(16) int   g_col[EMAX];
__device__ __align__(16) float g_nrm[EMAX];

// ---------------------------------------------------------------------------
// Small helpers
// ---------------------------------------------------------------------------
__device__ __forceinline__ unsigned long long pack2(float x, float y) {
    unsigned long long r;
    asm("mov.b64 %0, {%1, %2};" : "=l"(r) : "f"(x), "f"(y));
    return r;
}
__device__ __forceinline__ void unpack2(unsigned long long v, float& x, float& y) {
    asm("mov.b64 {%0, %1}, %2;" : "=f"(x), "=f"(y) : "l"(v));
}
// Packed dual-FMA (SASS FFMA2): d = a * b + d on two f32 lanes.
__device__ __forceinline__ void fma2(unsigned long long& d, unsigned long long a,
                                     unsigned long long b) {
    asm("fma.rn.f32x2 %0, %1, %2, %0;" : "+l"(d) : "l"(a), "l"(b));
}
// Vectorized global reduction (sm_90+): 1 REDG.128 instead of 4 REDG.32
__device__ __forceinline__ void red_add_v4(float4* addr, float4 v) {
    asm volatile("red.global.add.v4.f32 [%0], {%1, %2, %3, %4};"
                 :: "l"(addr), "f"(v.x), "f"(v.y), "f"(v.z), "f"(v.w)
                 : "memory");
}

// ---------------------------------------------------------------------------
// Degree / norm preparation  (edge_index is int32: JAX x64 is disabled, so
// the reference's jnp.int64 arrays materialize as int32)
// ---------------------------------------------------------------------------
__global__ void deg_init_kernel(float* __restrict__ deg, int n) {
    int i = blockIdx.x * blockDim.x + threadIdx.x;
    if (i < n) deg[i] = 1.0f;   // self-loop weight
}

__global__ void deg_accum_kernel(const int* __restrict__ ei,
                                 const float* __restrict__ w,
                                 float* __restrict__ deg, int E, int n) {
    int e = blockIdx.x * blockDim.x + threadIdx.x;
    if (e < E) {
        int c = ei[E + e];
        if ((unsigned)c < (unsigned)n) atomicAdd(&deg[c], w[e]);
    }
}

__global__ void dinv_kernel(const float* __restrict__ deg,
                            float* __restrict__ dinv,
                            float* __restrict__ sn, int n) {
    int i = blockIdx.x * blockDim.x + threadIdx.x;
    if (i < n) {
        float d = deg[i];
        float v = d > 0.f ? rsqrtf(d) : 0.f;
        dinv[i] = v;
        sn[i] = v * v;
    }
}

__global__ void edge_prep_kernel(const int* __restrict__ ei,
                                 const float* __restrict__ w,
                                 const float* __restrict__ dinv,
                                 int* __restrict__ row, int* __restrict__ col,
                                 float* __restrict__ nrm, int E, int n) {
    int e = blockIdx.x * blockDim.x + threadIdx.x;
    if (e < E) {
        int r = ei[e];
        int c = ei[E + e];
        bool ok = ((unsigned)r < (unsigned)n) && ((unsigned)c < (unsigned)n);
        row[e] = ok ? r : 0;
        col[e] = ok ? c : 0;
        nrm[e] = ok ? dinv[r] * w[e] * dinv[c] : 0.f;
    }
}

// ---------------------------------------------------------------------------
// SGEMM: C[M,Nc] = epiA(A[M,K]) @ W[K,Nc] (+ cbias)
//   A_BIAS:  A-elementwise  a += ab[k]
//   A_RELU:  a = max(a, 0)
//   C_BIAS:  c += cb[n]
//   C_SELF:  also write C2 = c * sn[row]  (self-loop init of aggregation buf)
// 128x128 tile, BK=16, 256 threads, 8x8 per thread, inner loop in f32x2 FMA.
// ---------------------------------------------------------------------------
template <bool A_BIAS, bool A_RELU, bool C_BIAS, bool C_SELF>
__global__ __launch_bounds__(256, 2)
void gemm_kernel(const float* __restrict__ A, const float* __restrict__ W,
                 const float* __restrict__ ab, const float* __restrict__ cb,
                 const float* __restrict__ sn,
                 float* __restrict__ C, float* __restrict__ C2,
                 int M, int K, int Nc) {
    __shared__ __align__(16) float As[16][132];  // transposed: As[k][row]
    __shared__ __align__(16) float Bs[16][132];  // Bs[k][col]

    const int tid = threadIdx.x;
    const int tx = tid & 15;
    const int ty = tid >> 4;
    const int rowBase = blockIdx.y * 128;
    const int colBase = blockIdx.x * 128;

    unsigned long long acc2[8][4];
#pragma unroll
    for (int i = 0; i < 8; ++i)
#pragma unroll
        for (int j = 0; j < 4; ++j) acc2[i][j] = 0ull;

    for (int k0 = 0; k0 < K; k0 += 16) {
        // ---- load A tile (with optional bias/relu), store transposed ----
#pragma unroll
        for (int it = 0; it < 2; ++it) {
            int lin = tid + it * 256;         // 0..511 float4 slots
            int arow = lin >> 2;              // 0..127
            int acq  = lin & 3;               // 0..3 (float4 within the 16 k's)
            int grow = rowBase + arow;
            float4 v = make_float4(0.f, 0.f, 0.f, 0.f);
            if (grow < M)
                v = *(const float4*)(A + (size_t)grow * K + k0 + acq * 4);
            if (A_BIAS) {
                float4 bb = *(const float4*)(ab + k0 + acq * 4);
                v.x += bb.x; v.y += bb.y; v.z += bb.z; v.w += bb.w;
            }
            if (A_RELU) {
                v.x = fmaxf(v.x, 0.f); v.y = fmaxf(v.y, 0.f);
                v.z = fmaxf(v.z, 0.f); v.w = fmaxf(v.w, 0.f);
            }
            As[acq * 4 + 0][arow] = v.x;
            As[acq * 4 + 1][arow] = v.y;
            As[acq * 4 + 2][arow] = v.z;
            As[acq * 4 + 3][arow] = v.w;
        }
        // ---- load B tile ----
#pragma unroll
        for (int it = 0; it < 2; ++it) {
            int lin = tid + it * 256;
            int brow = lin >> 5;              // 0..15
            int bcq  = lin & 31;              // 0..31 float4s per row
            float4 v = *(const float4*)(W + (size_t)(k0 + brow) * Nc + colBase + bcq * 4);
            *(float4*)&Bs[brow][bcq * 4] = v;
        }
        __syncthreads();

#pragma unroll
        for (int k = 0; k < 16; ++k) {
            float a[8], b[8];
            *(float4*)&a[0] = *(const float4*)&As[k][ty * 8];
            *(float4*)&a[4] = *(const float4*)&As[k][ty * 8 + 4];
            *(float4*)&b[0] = *(const float4*)&Bs[k][tx * 8];
            *(float4*)&b[4] = *(const float4*)&Bs[k][tx * 8 + 4];
            unsigned long long b2[4];
#pragma unroll
            for (int j = 0; j < 4; ++j) b2[j] = pack2(b[2 * j], b[2 * j + 1]);
#pragma unroll
            for (int i = 0; i < 8; ++i) {
                unsigned long long aa = pack2(a[i], a[i]);
#pragma unroll
                for (int j = 0; j < 4; ++j) fma2(acc2[i][j], aa, b2[j]);
            }
        }
        __syncthreads();
    }

    // ---- epilogue ----
#pragma unroll
    for (int i = 0; i < 8; ++i) {
        int grow = rowBase + ty * 8 + i;
        if (grow >= M) break;
        float cv[8];
#pragma unroll
        for (int j = 0; j < 4; ++j) unpack2(acc2[i][j], cv[2 * j], cv[2 * j + 1]);
        if (C_BIAS) {
#pragma unroll
            for (int j = 0; j < 8; ++j) cv[j] += cb[colBase + tx * 8 + j];
        }
        float* cptr = C + (size_t)grow * Nc + colBase + tx * 8;
        *(float4*)cptr       = make_float4(cv[0], cv[1], cv[2], cv[3]);
        *(float4*)(cptr + 4) = make_float4(cv[4], cv[5], cv[6], cv[7]);
        if (C_SELF) {
            float s = sn[grow];
            float* c2 = C2 + (size_t)grow * Nc + colBase + tx * 8;
            *(float4*)c2       = make_float4(cv[0] * s, cv[1] * s, cv[2] * s, cv[3] * s);
            *(float4*)(c2 + 4) = make_float4(cv[4] * s, cv[5] * s, cv[6] * s, cv[7] * s);
        }
    }
}

// ---------------------------------------------------------------------------
// Edge aggregation: out[col[e], :] += H[row[e], :] * nrm[e]
// One warp per edge, float4 gather + red.global.add.v4.f32 scatter.
// ---------------------------------------------------------------------------
template <int D>
__global__ __launch_bounds__(256)
void agg_kernel(const float* __restrict__ H, const int* __restrict__ row,
                const int* __restrict__ col, const float* __restrict__ nrm,
                float* __restrict__ out, int E) {
    int w = (blockIdx.x * 256 + threadIdx.x) >> 5;
    int lane = threadIdx.x & 31;
    if (w >= E) return;
    int r = __ldg(&row[w]);
    int c = __ldg(&col[w]);
    float nm = __ldg(&nrm[w]);
    const float4* src = (const float4*)(H + (size_t)r * D);
    float4* dst = (float4*)(out + (size_t)c * D);
#pragma unroll
    for (int it = 0; it < D / 128; ++it) {
        float4 v = src[lane + it * 32];
        v.x *= nm; v.y *= nm; v.z *= nm; v.w *= nm;
        red_add_v4(dst + lane + it * 32, v);
    }
}

// ---------------------------------------------------------------------------
// Launcher
// ---------------------------------------------------------------------------
extern "C" void kernel_launch(void* const* d_in, const int* in_sizes, int n_in,
                              void* d_out, int out_size) {
    const float* x  = (const float*)d_in[0];
    const int*   ei = (const int*)d_in[1];     // int32! (JAX x64 disabled)
    const float* ew = (const float*)d_in[2];
    const float* W1 = (const float*)d_in[3];
    const float* b1 = (const float*)d_in[4];
    const float* W2 = (const float*)d_in[5];
    const float* b2 = (const float*)d_in[6];
    const float* Wp = (const float*)d_in[7];
    const float* bp = (const float*)d_in[8];
    float* out = (float*)d_out;

    const int M = in_sizes[0] / 512;   // 50000
    const int E = in_sizes[2];         // 800000

    float *deg, *dinv, *sn, *H1, *AG1, *H2, *AG2, *nrm;
    int *rw, *cl;
    cudaGetSymbolAddress((void**)&deg,  g_deg);
    cudaGetSymbolAddress((void**)&dinv, g_dinv);
    cudaGetSymbolAddress((void**)&sn,   g_sn);
    cudaGetSymbolAddress((void**)&H1,   g_H1);
    cudaGetSymbolAddress((void**)&AG1,  g_AG1);
    cudaGetSymbolAddress((void**)&H2,   g_H2);
    cudaGetSymbolAddress((void**)&AG2,  g_AG2);
    cudaGetSymbolAddress((void**)&rw,   g_row);
    cudaGetSymbolAddress((void**)&cl,   g_col);
    cudaGetSymbolAddress((void**)&nrm,  g_nrm);

    const int TB = 256;
    // norm prep
    deg_init_kernel<<<(M + TB - 1) / TB, TB>>>(deg, M);
    deg_accum_kernel<<<(E + TB - 1) / TB, TB>>>(ei, ew, deg, E, M);
    dinv_kernel<<<(M + TB - 1) / TB, TB>>>(deg, dinv, sn, M);
    edge_prep_kernel<<<(E + TB - 1) / TB, TB>>>(ei, ew, dinv, rw, cl, nrm, E, M);

    const int rowBlocks = (M + 127) / 128;

    // layer 1: H1 = x @ W1 ; AG1 = H1*sn (self loop) ; AG1 += edges
    gemm_kernel<false, false, false, true>
        <<<dim3(256 / 128, rowBlocks), 256>>>(x, W1, nullptr, nullptr, sn,
                                              H1, AG1, M, 512, 256);
    agg_kernel<256><<<(E + 7) / 8, 256>>>(H1, rw, cl, nrm, AG1, E);

    // layer 2: H2 = relu(AG1 + b1) @ W2 ; AG2 = H2*sn ; AG2 += edges
    gemm_kernel<true, true, false, true>
        <<<dim3(1, rowBlocks), 256>>>(AG1, W2, b1, nullptr, sn,
                                      H2, AG2, M, 256, 128);
    agg_kernel<128><<<(E + 7) / 8, 256>>>(H2, rw, cl, nrm, AG2, E);

    // projection: out = (AG2 + b2) @ Wp + bp
    gemm_kernel<true, false, true, false>
        <<<dim3(1, rowBlocks), 256>>>(AG2, Wp, b2, bp, nullptr,
                                      out, nullptr, M, 128, 128);
}

// round 5
// speedup vs baseline: 1.2048x; 1.2048x over previous
#include <cuda_runtime.h>
#include <cstdint>

// Problem constants (shapes fixed by the dataset)
static constexpr int NMAX = 50000;
static constexpr int EMAX = 800000;

// Scratch (static device allocations — no cudaMalloc allowed).
__device__ __align__(16) float g_deg[NMAX];
__device__ __align__(16) float g_dinv[NMAX];
__device__ __align__(16) float g_sn[NMAX];                 // dinv^2 (self-loop norm)
__device__ __align__(16) float g_H1[(size_t)NMAX * 256];   // x @ W1
__device__ __align__(16) float g_AG1[(size_t)NMAX * 256];  // aggregated layer1
__device__ __align__(16) float g_H2[(size_t)NMAX * 128];   // relu(AG1+b1) @ W2
__device__ __align__(16) float g_AG2[(size_t)NMAX * 128];  // aggregated layer2
__device__ __align__(16) int   g_cnt[NMAX];                // in-degree histogram
__device__ __align__(16) int   g_rowptr[NMAX + 1];         // CSR offsets (by dst)
__device__ __align__(16) int   g_fill[NMAX];               // scatter cursors
__device__ __align__(16) int   g_src[EMAX];                // CSR: source node per edge
__device__ __align__(16) float g_wgt[EMAX];                // CSR: norm per edge

// ---------------------------------------------------------------------------
// Small helpers
// ---------------------------------------------------------------------------
__device__ __forceinline__ unsigned long long pack2(float x, float y) {
    unsigned long long r;
    asm("mov.b64 %0, {%1, %2};" : "=l"(r) : "f"(x), "f"(y));
    return r;
}
__device__ __forceinline__ void unpack2(unsigned long long v, float& x, float& y) {
    asm("mov.b64 {%0, %1}, %2;" : "=f"(x), "=f"(y) : "l"(v));
}
// Packed dual-FMA (SASS FFMA2): d = a * b + d on two f32 lanes.
__device__ __forceinline__ void fma2(unsigned long long& d, unsigned long long a,
                                     unsigned long long b) {
    asm("fma.rn.f32x2 %0, %1, %2, %0;" : "+l"(d) : "l"(a), "l"(b));
}

// ---------------------------------------------------------------------------
// Degree / histogram preparation (edge_index is int32: JAX x64 disabled)
// ---------------------------------------------------------------------------
__global__ void deg_init_kernel(float* __restrict__ deg, int* __restrict__ cnt,
                                int n) {
    int i = blockIdx.x * blockDim.x + threadIdx.x;
    if (i < n) { deg[i] = 1.0f; cnt[i] = 0; }   // self-loop weight = 1
}

__global__ void deg_accum_kernel(const int* __restrict__ ei,
                                 const float* __restrict__ w,
                                 float* __restrict__ deg, int* __restrict__ cnt,
                                 int E, int n) {
    int e = blockIdx.x * blockDim.x + threadIdx.x;
    if (e < E) {
        int c = ei[E + e];
        if ((unsigned)c < (unsigned)n) {
            atomicAdd(&deg[c], w[e]);
            atomicAdd(&cnt[c], 1);
        }
    }
}

__global__ void dinv_kernel(const float* __restrict__ deg,
                            float* __restrict__ dinv,
                            float* __restrict__ sn, int n) {
    int i = blockIdx.x * blockDim.x + threadIdx.x;
    if (i < n) {
        float d = deg[i];
        float v = d > 0.f ? rsqrtf(d) : 0.f;
        dinv[i] = v;
        sn[i] = v * v;
    }
}

// Single-block exclusive scan over cnt -> rowptr (and fill copy). n up to 50000.
__global__ __launch_bounds__(1024)
void scan_kernel(const int* __restrict__ cnt, int* __restrict__ rowptr,
                 int* __restrict__ fill, int n) {
    __shared__ int wsum[32];
    __shared__ int wpre[32];
    const int t = threadIdx.x, lane = t & 31, wid = t >> 5;
    int run = 0;
    for (int base = 0; base < n; base += 1024) {
        int i = base + t;
        int v = (i < n) ? cnt[i] : 0;
        int s = v;
#pragma unroll
        for (int o = 1; o < 32; o <<= 1) {
            int u = __shfl_up_sync(0xffffffffu, s, o);
            if (lane >= o) s += u;
        }
        if (lane == 31) wsum[wid] = s;
        __syncthreads();
        if (wid == 0) {
            int ws = wsum[lane];
#pragma unroll
            for (int o = 1; o < 32; o <<= 1) {
                int u = __shfl_up_sync(0xffffffffu, ws, o);
                if (lane >= o) ws += u;
            }
            wpre[lane] = ws;
        }
        __syncthreads();
        int excl = run + (wid ? wpre[wid - 1] : 0) + s - v;
        if (i < n) { rowptr[i] = excl; fill[i] = excl; }
        run += wpre[31];
        __syncthreads();
    }
    if (t == 0) rowptr[n] = run;
}

// Scatter edges into CSR (by destination), precomputing the GCN norm.
__global__ void scatter_kernel(const int* __restrict__ ei,
                               const float* __restrict__ w,
                               const float* __restrict__ dinv,
                               int* __restrict__ fill,
                               int* __restrict__ src, float* __restrict__ wgt,
                               int E, int n) {
    int e = blockIdx.x * blockDim.x + threadIdx.x;
    if (e < E) {
        int c = ei[E + e];
        if ((unsigned)c < (unsigned)n) {
            int r = ei[e];
            bool rok = (unsigned)r < (unsigned)n;
            float nm = rok ? dinv[r] * w[e] * dinv[c] : 0.f;
            int pos = atomicAdd(&fill[c], 1);
            src[pos] = rok ? r : 0;
            wgt[pos] = nm;
        }
    }
}

// ---------------------------------------------------------------------------
// SGEMM: C[M,Nc] = epiA(A[M,K]) @ W[K,Nc] (+ cbias)
// 128x128 tile, BK=16, 256 threads, 8x8 per thread, f32x2 FMA inner loop,
// register-prefetch double buffering of global loads.
// ---------------------------------------------------------------------------
template <bool A_BIAS, bool A_RELU, bool C_BIAS>
__global__ __launch_bounds__(256, 2)
void gemm_kernel(const float* __restrict__ A, const float* __restrict__ W,
                 const float* __restrict__ ab, const float* __restrict__ cb,
                 float* __restrict__ C, int M, int K, int Nc) {
    __shared__ __align__(16) float As[16][132];  // transposed: As[k][row]
    __shared__ __align__(16) float Bs[16][132];  // Bs[k][col]

    const int tid = threadIdx.x;
    const int tx = tid & 15;
    const int ty = tid >> 4;
    const int rowBase = blockIdx.y * 128;
    const int colBase = blockIdx.x * 128;

    // per-thread global load coordinates
    const int aRow0 = (tid * 2) >> 3;          // via lin = tid + it*256
    // (computed inline below)

    unsigned long long acc2[8][4];
#pragma unroll
    for (int i = 0; i < 8; ++i)
#pragma unroll
        for (int j = 0; j < 4; ++j) acc2[i][j] = 0ull;

    float4 pa[2], pb[2];

    auto loadTile = [&](int k0) {
#pragma unroll
        for (int it = 0; it < 2; ++it) {
            int lin = tid + it * 256;
            int arow = lin >> 2;
            int acq  = lin & 3;
            int grow = rowBase + arow;
            float4 v = make_float4(0.f, 0.f, 0.f, 0.f);
            if (grow < M)
                v = *(const float4*)(A + (size_t)grow * K + k0 + acq * 4);
            if (A_BIAS) {
                float4 bb = *(const float4*)(ab + k0 + acq * 4);
                v.x += bb.x; v.y += bb.y; v.z += bb.z; v.w += bb.w;
            }
            if (A_RELU) {
                v.x = fmaxf(v.x, 0.f); v.y = fmaxf(v.y, 0.f);
                v.z = fmaxf(v.z, 0.f); v.w = fmaxf(v.w, 0.f);
            }
            pa[it] = v;

            int brow = lin >> 5;
            int bcq  = lin & 31;
            pb[it] = *(const float4*)(W + (size_t)(k0 + brow) * Nc + colBase + bcq * 4);
        }
    };
    auto storeTile = [&]() {
#pragma unroll
        for (int it = 0; it < 2; ++it) {
            int lin = tid + it * 256;
            int arow = lin >> 2;
            int acq  = lin & 3;
            As[acq * 4 + 0][arow] = pa[it].x;
            As[acq * 4 + 1][arow] = pa[it].y;
            As[acq * 4 + 2][arow] = pa[it].z;
            As[acq * 4 + 3][arow] = pa[it].w;
            int brow = lin >> 5;
            int bcq  = lin & 31;
            *(float4*)&Bs[brow][bcq * 4] = pb[it];
        }
    };

    loadTile(0);
    for (int k0 = 0; k0 < K; k0 += 16) {
        storeTile();
        __syncthreads();
        if (k0 + 16 < K) loadTile(k0 + 16);

#pragma unroll
        for (int k = 0; k < 16; ++k) {
            float a[8], b[8];
            *(float4*)&a[0] = *(const float4*)&As[k][ty * 8];
            *(float4*)&a[4] = *(const float4*)&As[k][ty * 8 + 4];
            *(float4*)&b[0] = *(const float4*)&Bs[k][tx * 8];
            *(float4*)&b[4] = *(const float4*)&Bs[k][tx * 8 + 4];
            unsigned long long b2[4];
#pragma unroll
            for (int j = 0; j < 4; ++j) b2[j] = pack2(b[2 * j], b[2 * j + 1]);
#pragma unroll
            for (int i = 0; i < 8; ++i) {
                unsigned long long aa = pack2(a[i], a[i]);
#pragma unroll
                for (int j = 0; j < 4; ++j) fma2(acc2[i][j], aa, b2[j]);
            }
        }
        __syncthreads();
    }

    // ---- epilogue ----
#pragma unroll
    for (int i = 0; i < 8; ++i) {
        int grow = rowBase + ty * 8 + i;
        if (grow >= M) break;
        float cv[8];
#pragma unroll
        for (int j = 0; j < 4; ++j) unpack2(acc2[i][j], cv[2 * j], cv[2 * j + 1]);
        if (C_BIAS) {
#pragma unroll
            for (int j = 0; j < 8; ++j) cv[j] += cb[colBase + tx * 8 + j];
        }
        float* cptr = C + (size_t)grow * Nc + colBase + tx * 8;
        *(float4*)cptr       = make_float4(cv[0], cv[1], cv[2], cv[3]);
        *(float4*)(cptr + 4) = make_float4(cv[4], cv[5], cv[6], cv[7]);
    }
}

// ---------------------------------------------------------------------------
// CSR aggregation: one warp per destination node.
// AG[i,:] = sn[i]*H[i,:] + sum_{e in csr(i)} wgt[e] * H[src[e],:]
// Register accumulation, single write per row — no atomics at all.
// ---------------------------------------------------------------------------
template <int D>
__global__ __launch_bounds__(256)
void agg_csr_kernel(const float* __restrict__ H,
                    const int* __restrict__ rowptr,
                    const int* __restrict__ src,
                    const float* __restrict__ wgt,
                    const float* __restrict__ sn,
                    float* __restrict__ AG, int n) {
    constexpr int V = D / 128;   // float4s per lane
    int node = (blockIdx.x * 256 + threadIdx.x) >> 5;
    int lane = threadIdx.x & 31;
    if (node >= n) return;

    float s = __ldg(&sn[node]);
    const float4* hself = (const float4*)(H + (size_t)node * D);
    float4 acc[V];
#pragma unroll
    for (int v = 0; v < V; ++v) {
        float4 h = __ldg(&hself[lane + 32 * v]);
        acc[v] = make_float4(h.x * s, h.y * s, h.z * s, h.w * s);
    }

    int e0 = __ldg(&rowptr[node]);
    int e1 = __ldg(&rowptr[node + 1]);
    for (int e = e0; e < e1; ++e) {
        int r = __ldg(&src[e]);
        float nm = __ldg(&wgt[e]);
        const float4* hs = (const float4*)(H + (size_t)r * D);
#pragma unroll
        for (int v = 0; v < V; ++v) {
            float4 h = __ldg(&hs[lane + 32 * v]);
            acc[v].x += nm * h.x;
            acc[v].y += nm * h.y;
            acc[v].z += nm * h.z;
            acc[v].w += nm * h.w;
        }
    }

    float4* dst = (float4*)(AG + (size_t)node * D);
#pragma unroll
    for (int v = 0; v < V; ++v) dst[lane + 32 * v] = acc[v];
}

// ---------------------------------------------------------------------------
// Launcher
// ---------------------------------------------------------------------------
extern "C" void kernel_launch(void* const* d_in, const int* in_sizes, int n_in,
                              void* d_out, int out_size) {
    const float* x  = (const float*)d_in[0];
    const int*   ei = (const int*)d_in[1];     // int32 (JAX x64 disabled)
    const float* ew = (const float*)d_in[2];
    const float* W1 = (const float*)d_in[3];
    const float* b1 = (const float*)d_in[4];
    const float* W2 = (const float*)d_in[5];
    const float* b2 = (const float*)d_in[6];
    const float* Wp = (const float*)d_in[7];
    const float* bp = (const float*)d_in[8];
    float* out = (float*)d_out;

    const int M = in_sizes[0] / 512;   // 50000
    const int E = in_sizes[2];         // 800000

    float *deg, *dinv, *sn, *H1, *AG1, *H2, *AG2, *wgt;
    int *cnt, *rowptr, *fill, *src;
    cudaGetSymbolAddress((void**)&deg,    g_deg);
    cudaGetSymbolAddress((void**)&dinv,   g_dinv);
    cudaGetSymbolAddress((void**)&sn,     g_sn);
    cudaGetSymbolAddress((void**)&H1,     g_H1);
    cudaGetSymbolAddress((void**)&AG1,    g_AG1);
    cudaGetSymbolAddress((void**)&H2,     g_H2);
    cudaGetSymbolAddress((void**)&AG2,    g_AG2);
    cudaGetSymbolAddress((void**)&cnt,    g_cnt);
    cudaGetSymbolAddress((void**)&rowptr, g_rowptr);
    cudaGetSymbolAddress((void**)&fill,   g_fill);
    cudaGetSymbolAddress((void**)&src,    g_src);
    cudaGetSymbolAddress((void**)&wgt,    g_wgt);

    const int TB = 256;
    // ---- norm + CSR prep ----
    deg_init_kernel<<<(M + TB - 1) / TB, TB>>>(deg, cnt, M);
    deg_accum_kernel<<<(E + TB - 1) / TB, TB>>>(ei, ew, deg, cnt, E, M);
    dinv_kernel<<<(M + TB - 1) / TB, TB>>>(deg, dinv, sn, M);
    scan_kernel<<<1, 1024>>>(cnt, rowptr, fill, M);
    scatter_kernel<<<(E + TB - 1) / TB, TB>>>(ei, ew, dinv, fill, src, wgt, E, M);

    const int rowBlocks = (M + 127) / 128;
    const int aggBlocks = (M + 7) / 8;   // 8 warps/block

    // layer 1: H1 = x @ W1 ; AG1 = CSR-aggregate(H1)
    gemm_kernel<false, false, false>
        <<<dim3(2, rowBlocks), 256>>>(x, W1, nullptr, nullptr, H1, M, 512, 256);
    agg_csr_kernel<256><<<aggBlocks, 256>>>(H1, rowptr, src, wgt, sn, AG1, M);

    // layer 2: H2 = relu(AG1 + b1) @ W2 ; AG2 = CSR-aggregate(H2)
    gemm_kernel<true, true, false>
        <<<dim3(1, rowBlocks), 256>>>(AG1, W2, b1, nullptr, H2, M, 256, 128);
    agg_csr_kernel<128><<<aggBlocks, 256>>>(H2, rowptr, src, wgt, sn, AG2, M);

    // projection: out = (AG2 + b2) @ Wp + bp
    gemm_kernel<true, false, true>
        <<<dim3(1, rowBlocks), 256>>>(AG2, Wp, b2, bp, out, M, 128, 128);
}